// round 1
// baseline (speedup 1.0000x reference)
#include <cuda_runtime.h>
#include <math.h>

#define C_IN   64
#define C_OUT  64
#define NBASIS 9
#define TILE_T 64
#define MAX_T  1600000
#define MAX_F  400000
#define BN_EPS 1e-3f

// ---- scratch (device globals; no allocation allowed) ----
__device__ float g_contrib[(size_t)MAX_T * C_OUT];   // 409.6 MB
__device__ float g_prebn[(size_t)MAX_F * C_OUT];     // 102.4 MB
__device__ int   g_offs[MAX_F];
__device__ int   g_blk[1024];
__device__ float g_stats[2 * C_OUT];

// ================= exclusive-scan of num_texture =================
__global__ void scan1_kernel(const int* __restrict__ cnt, int F) {
    __shared__ int s[1024];
    int tid = threadIdx.x;
    int f = blockIdx.x * 1024 + tid;
    int c = (f < F) ? cnt[f] : 0;
    s[tid] = c;
    __syncthreads();
    for (int off = 1; off < 1024; off <<= 1) {
        int v = (tid >= off) ? s[tid - off] : 0;
        __syncthreads();
        s[tid] += v;
        __syncthreads();
    }
    if (f < F) g_offs[f] = s[tid] - c;          // exclusive within block
    if (tid == 1023) g_blk[blockIdx.x] = s[1023];
}

__global__ void scan2_kernel(int nb) {
    __shared__ int s[1024];
    int tid = threadIdx.x;
    int c = (tid < nb) ? g_blk[tid] : 0;
    s[tid] = c;
    __syncthreads();
    for (int off = 1; off < 1024; off <<= 1) {
        int v = (tid >= off) ? s[tid - off] : 0;
        __syncthreads();
        s[tid] += v;
        __syncthreads();
    }
    if (tid < nb) g_blk[tid] = s[tid] - c;      // exclusive block prefix
}

__global__ void scan3_kernel(int F) {
    int f = blockIdx.x * 1024 + threadIdx.x;
    if (f < F) g_offs[f] += g_blk[blockIdx.x];
}

// ================= main GEMM: contrib[t,o] = sum_k bary[t,k] * sum_i x[t,i]*W[o,i,k] ===
// Persistent CTAs (1/SM), W resident in SMEM, 64-texture tiles, 4x4 micro-tiles.
#define SMEM_W_FLOATS  (NBASIS * C_IN * C_OUT)         // 36864
#define SMEM_X_FLOATS  (C_IN * 65)                     // 4160 (padded stride 65)
#define SMEM_B_FLOATS  (TILE_T * NBASIS)               // 576
#define SMEM_BYTES     ((SMEM_W_FLOATS + SMEM_X_FLOATS + SMEM_B_FLOATS) * 4)

__global__ void __launch_bounds__(256, 1) gemm_kernel(
    const float* __restrict__ X,     // [T, 64]
    const float* __restrict__ BARY,  // [T, 9]
    const float* __restrict__ W,     // [64, 64, 9]  (o, i, k)
    int T, int numTiles)
{
    extern __shared__ float sm[];
    float* Ws = sm;                      // [k][i][o]  ((k*64+i)*64+o)
    float* Xs = sm + SMEM_W_FLOATS;      // [i][t]     (i*65 + t)
    float* Bs = Xs + SMEM_X_FLOATS;      // [t][k]

    const int tid = threadIdx.x;

    // Load W once per block, transposed to [k][i][o] so o is contiguous.
    for (int idx = tid; idx < SMEM_W_FLOATS; idx += 256) {
        int o = idx / (C_IN * NBASIS);
        int r = idx - o * (C_IN * NBASIS);
        int i = r / NBASIS;
        int k = r - i * NBASIS;
        Ws[(k * C_IN + i) * C_OUT + o] = W[idx];
    }
    __syncthreads();

    const int tx = tid & 15;         // output group: o = tx*4 .. tx*4+3
    const int ty = tid >> 4;         // texture group: t = tLoc .. tLoc+3
    const int oBase = tx * 4;
    const int tLoc  = ty * 4;

    for (int tile = blockIdx.x; tile < numTiles; tile += gridDim.x) {
        const int t0 = tile * TILE_T;

        // X tile, transposed into [i][t] with pad-65 stride (conflict-free stores)
        for (int idx = tid; idx < TILE_T * C_IN; idx += 256) {
            int tt = idx >> 6;
            int ii = idx & 63;
            int t = t0 + tt;
            Xs[ii * 65 + tt] = (t < T) ? X[(size_t)t * C_IN + ii] : 0.0f;
        }
        // bary tile
        for (int idx = tid; idx < TILE_T * NBASIS; idx += 256) {
            int tt = idx / NBASIS;
            int kk = idx - tt * NBASIS;
            int t = t0 + tt;
            Bs[tt * NBASIS + kk] = (t < T) ? BARY[(size_t)t * NBASIS + kk] : 0.0f;
        }
        __syncthreads();

        float acc[4][4];
        #pragma unroll
        for (int a = 0; a < 4; a++)
            #pragma unroll
            for (int b = 0; b < 4; b++) acc[a][b] = 0.0f;

        #pragma unroll 1
        for (int k = 0; k < NBASIS; k++) {
            float a2[4][4];
            #pragma unroll
            for (int a = 0; a < 4; a++)
                #pragma unroll
                for (int b = 0; b < 4; b++) a2[a][b] = 0.0f;

            const float* wk = Ws + k * (C_IN * C_OUT);
            #pragma unroll 8
            for (int i = 0; i < C_IN; i++) {
                float4 w = *(const float4*)(wk + i * C_OUT + oBase);
                float x0 = Xs[i * 65 + tLoc + 0];
                float x1 = Xs[i * 65 + tLoc + 1];
                float x2 = Xs[i * 65 + tLoc + 2];
                float x3 = Xs[i * 65 + tLoc + 3];
                a2[0][0] += x0 * w.x; a2[0][1] += x0 * w.y; a2[0][2] += x0 * w.z; a2[0][3] += x0 * w.w;
                a2[1][0] += x1 * w.x; a2[1][1] += x1 * w.y; a2[1][2] += x1 * w.z; a2[1][3] += x1 * w.w;
                a2[2][0] += x2 * w.x; a2[2][1] += x2 * w.y; a2[2][2] += x2 * w.z; a2[2][3] += x2 * w.w;
                a2[3][0] += x3 * w.x; a2[3][1] += x3 * w.y; a2[3][2] += x3 * w.z; a2[3][3] += x3 * w.w;
            }
            #pragma unroll
            for (int ttq = 0; ttq < 4; ttq++) {
                float b = Bs[(tLoc + ttq) * NBASIS + k];
                acc[ttq][0] += b * a2[ttq][0];
                acc[ttq][1] += b * a2[ttq][1];
                acc[ttq][2] += b * a2[ttq][2];
                acc[ttq][3] += b * a2[ttq][3];
            }
        }

        #pragma unroll
        for (int ttq = 0; ttq < 4; ttq++) {
            int t = t0 + tLoc + ttq;
            if (t < T) {
                float4 v = make_float4(acc[ttq][0], acc[ttq][1], acc[ttq][2], acc[ttq][3]);
                *(float4*)&g_contrib[(size_t)t * C_OUT + oBase] = v;
            }
        }
        __syncthreads();
    }
}

// ================= facet mean + bias + relu =================
__global__ void facet_kernel(const int* __restrict__ cnt,
                             const float* __restrict__ bias, int F) {
    int gw   = (blockIdx.x * blockDim.x + threadIdx.x) >> 5;
    int lane = threadIdx.x & 31;
    int nw   = (gridDim.x * blockDim.x) >> 5;
    float b0 = bias[lane];
    float b1 = bias[lane + 32];
    for (int f = gw; f < F; f += nw) {
        int start = g_offs[f];
        int c = cnt[f];
        float s0 = 0.0f, s1 = 0.0f;
        for (int r = 0; r < c; r++) {
            const float* row = g_contrib + (size_t)(start + r) * C_OUT;
            s0 += row[lane];
            s1 += row[lane + 32];
        }
        float inv = (c > 0) ? (1.0f / (float)c) : 0.0f;
        float v0 = fmaxf(s0 * inv + b0, 0.0f);
        float v1 = fmaxf(s1 * inv + b1, 0.0f);
        g_prebn[(size_t)f * C_OUT + lane]      = v0;
        g_prebn[(size_t)f * C_OUT + lane + 32] = v1;
    }
}

// ================= batchnorm stats =================
__global__ void zero_stats_kernel() {
    if (threadIdx.x < 2 * C_OUT) g_stats[threadIdx.x] = 0.0f;
}

__global__ void stats_kernel(int F) {
    int o = threadIdx.x & 63;
    int g = threadIdx.x >> 6;            // 0..3
    float s = 0.0f, q = 0.0f;
    int stride = gridDim.x * 4;
    for (int f = blockIdx.x * 4 + g; f < F; f += stride) {
        float v = g_prebn[(size_t)f * C_OUT + o];
        s += v;
        q += v * v;
    }
    __shared__ float ss[4][64], sq[4][64];
    ss[g][o] = s; sq[g][o] = q;
    __syncthreads();
    if (g == 0) {
        s = ss[0][o] + ss[1][o] + ss[2][o] + ss[3][o];
        q = sq[0][o] + sq[1][o] + sq[2][o] + sq[3][o];
        atomicAdd(&g_stats[o], s);
        atomicAdd(&g_stats[C_OUT + o], q);
    }
}

// ================= batchnorm apply =================
__global__ void bn_kernel(const float* __restrict__ gamma,
                          const float* __restrict__ beta,
                          float* __restrict__ out, int F) {
    int idx = blockIdx.x * blockDim.x + threadIdx.x;   // float4 index
    int total = F * (C_OUT / 4);
    float invF = 1.0f / (float)F;
    for (; idx < total; idx += gridDim.x * blockDim.x) {
        int o = (idx & 15) * 4;
        float4 v = *(const float4*)&g_prebn[(size_t)idx * 4];
        float4 r;
        #pragma unroll
        for (int j = 0; j < 4; j++) {
            float mu  = g_stats[o + j] * invF;
            float var = g_stats[C_OUT + o + j] * invF - mu * mu;
            float sc  = rsqrtf(var + BN_EPS) * gamma[o + j];
            float bb  = beta[o + j];
            float x   = (&v.x)[j];
            (&r.x)[j] = (x - mu) * sc + bb;
        }
        *(float4*)&out[(size_t)idx * 4] = r;
    }
}

// ================= launch =================
extern "C" void kernel_launch(void* const* d_in, const int* in_sizes, int n_in,
                              void* d_out, int out_size) {
    const float* X     = (const float*)d_in[0];
    const float* BARY  = (const float*)d_in[1];
    const float* W     = (const float*)d_in[2];
    const float* bias  = (const float*)d_in[3];
    const float* gamma = (const float*)d_in[4];
    const float* beta  = (const float*)d_in[5];
    const int*   cnt   = (const int*)d_in[6];

    int T = in_sizes[0] / C_IN;
    int F = in_sizes[6];
    int numTiles = (T + TILE_T - 1) / TILE_T;

    int sms = 148;
    cudaDeviceGetAttribute(&sms, cudaDevAttrMultiProcessorCount, 0);
    cudaFuncSetAttribute(gemm_kernel, cudaFuncAttributeMaxDynamicSharedMemorySize, SMEM_BYTES);

    int nb = (F + 1023) / 1024;
    scan1_kernel<<<nb, 1024>>>(cnt, F);
    scan2_kernel<<<1, 1024>>>(nb);
    scan3_kernel<<<nb, 1024>>>(F);

    gemm_kernel<<<sms, 256, SMEM_BYTES>>>(X, BARY, W, T, numTiles);

    int facetBlocks = (F + 7) / 8;       // 8 warps per block, 1 facet per warp
    facet_kernel<<<facetBlocks, 256>>>(cnt, bias, F);

    zero_stats_kernel<<<1, 128>>>();
    stats_kernel<<<512, 256>>>(F);
    bn_kernel<<<2048, 256>>>(gamma, beta, (float*)d_out, F);
}

// round 3
// speedup vs baseline: 4.8492x; 4.8492x over previous
#include <cuda_runtime.h>
#include <cuda_fp16.h>
#include <math.h>
#include <stdint.h>

#define C_IN   64
#define C_OUT  64
#define NBASIS 9
#define TILE_M 256
#define MAX_T  1600000
#define MAX_F  400000
#define BN_EPS 1e-3f

// ---- scratch (device globals; no allocation allowed) ----
__device__ float g_contrib[(size_t)MAX_T * C_OUT];   // 409.6 MB
__device__ float g_prebn[(size_t)MAX_F * C_OUT];     // 102.4 MB
__device__ int   g_offs[MAX_F];
__device__ int   g_blk[1024];
__device__ float g_stats[2 * C_OUT];

// ================= exclusive-scan of num_texture =================
__global__ void scan1_kernel(const int* __restrict__ cnt, int F) {
    __shared__ int s[1024];
    int tid = threadIdx.x;
    int f = blockIdx.x * 1024 + tid;
    int c = (f < F) ? cnt[f] : 0;
    s[tid] = c;
    __syncthreads();
    for (int off = 1; off < 1024; off <<= 1) {
        int v = (tid >= off) ? s[tid - off] : 0;
        __syncthreads();
        s[tid] += v;
        __syncthreads();
    }
    if (f < F) g_offs[f] = s[tid] - c;
    if (tid == 1023) g_blk[blockIdx.x] = s[1023];
}
__global__ void scan2_kernel(int nb) {
    __shared__ int s[1024];
    int tid = threadIdx.x;
    int c = (tid < nb) ? g_blk[tid] : 0;
    s[tid] = c;
    __syncthreads();
    for (int off = 1; off < 1024; off <<= 1) {
        int v = (tid >= off) ? s[tid - off] : 0;
        __syncthreads();
        s[tid] += v;
        __syncthreads();
    }
    if (tid < nb) g_blk[tid] = s[tid] - c;
}
__global__ void scan3_kernel(int F) {
    int f = blockIdx.x * 1024 + threadIdx.x;
    if (f < F) g_offs[f] += g_blk[blockIdx.x];
}

// ================= mma.sync GEMM =================
// contrib[t,o] = sum_k bary[t,k] * ( sum_i x[t,i] * W[o,i,k] )
// Per basis k: tacc[32x32] = A[32,64] (x fp16) x B_k[64,32]^T (W fp16), fp32 acc.
// Then acc += bary_k * tacc  (bary stays fp32).
//
// SMEM (halves padded to stride 72 = conflict-free for ldsm-free 32b frag loads):
//   Wh : [(k*64 + o)*72 + i]   9*64*72*2  = 82944 B
//   Ax : [t*72 + i]            256*72*2   = 36864 B
//   Bs : [t*9 + k] fp32        256*9*4    =  9216 B
#define SM_WH   0
#define SM_AX   82944
#define SM_BS   119808
#define SMEM_GEMM 129024

#define MMA16816(d, a, b0, b1)                                              \
    asm volatile(                                                           \
        "mma.sync.aligned.m16n8k16.row.col.f32.f16.f16.f32 "                \
        "{%0,%1,%2,%3},{%4,%5,%6,%7},{%8,%9},{%0,%1,%2,%3};"                \
        : "+f"((d)[0]), "+f"((d)[1]), "+f"((d)[2]), "+f"((d)[3])            \
        : "r"((a)[0]), "r"((a)[1]), "r"((a)[2]), "r"((a)[3]),               \
          "r"(b0), "r"(b1))

__global__ void __launch_bounds__(512, 1) gemm_mma_kernel(
    const float* __restrict__ X,     // [T, 64]
    const float* __restrict__ BARY,  // [T, 9]
    const float* __restrict__ W,     // [64, 64, 9]  (o, i, k)
    int T, int numTiles)
{
    extern __shared__ char sm[];
    __half* Wh = (__half*)(sm + SM_WH);
    __half* Ax = (__half*)(sm + SM_AX);
    float*  Bs = (float*)(sm + SM_BS);

    const int tid  = threadIdx.x;
    const int wid  = tid >> 5;
    const int lane = tid & 31;
    const int gid  = lane >> 2;     // group id (0..7)
    const int tid4 = lane & 3;      // thread in group
    const int warp_m = wid >> 1;    // 0..7 : 32-row band
    const int warp_n = wid & 1;     // 0..1 : 32-col band

    // ---- convert W once: Wh[k][o][i] fp16 ----
    for (int idx = tid; idx < C_OUT * C_IN * NBASIS; idx += 512) {
        int o   = idx / (C_IN * NBASIS);
        int rem = idx - o * (C_IN * NBASIS);
        int i   = rem / NBASIS;
        int k   = rem - i * NBASIS;
        Wh[(k * 64 + o) * 72 + i] = __float2half_rn(W[idx]);
    }
    __syncthreads();

    const int rbase = warp_m * 32;

    for (int tile = blockIdx.x; tile < numTiles; tile += gridDim.x) {
        const int t0 = tile * TILE_M;

        // ---- load X tile -> fp16 Ax[t][i] (each thread: one row-half) ----
        {
            int row = tid >> 1;
            int hf  = tid & 1;
            int t = t0 + row;
            uint32_t pk[16];
            if (t < T) {
                const float4* xp = (const float4*)(X + (size_t)t * C_IN + hf * 32);
                #pragma unroll
                for (int j = 0; j < 8; j++) {
                    float4 v = xp[j];
                    __half2 h0 = __floats2half2_rn(v.x, v.y);
                    __half2 h1 = __floats2half2_rn(v.z, v.w);
                    pk[2 * j]     = *(uint32_t*)&h0;
                    pk[2 * j + 1] = *(uint32_t*)&h1;
                }
            } else {
                #pragma unroll
                for (int j = 0; j < 16; j++) pk[j] = 0u;
            }
            uint4* dst = (uint4*)(Ax + row * 72 + hf * 32);
            #pragma unroll
            for (int c = 0; c < 4; c++)
                dst[c] = make_uint4(pk[4 * c], pk[4 * c + 1], pk[4 * c + 2], pk[4 * c + 3]);
        }
        // ---- bary tile (fp32) ----
        {
            int limit = (T - t0) * NBASIS;   // may exceed tile; clamp below
            for (int idx = tid; idx < TILE_M * NBASIS; idx += 512)
                Bs[idx] = (idx < limit) ? BARY[(size_t)t0 * NBASIS + idx] : 0.0f;
        }
        __syncthreads();

        // ---- A fragments (once per tile, reused for all 9 bases) ----
        uint32_t afr[2][4][4];
        #pragma unroll
        for (int mt = 0; mt < 2; mt++) {
            int r = rbase + mt * 16 + gid;
            #pragma unroll
            for (int ks = 0; ks < 4; ks++) {
                int kk = ks * 16 + tid4 * 2;
                afr[mt][ks][0] = *(const uint32_t*)(Ax + r * 72 + kk);
                afr[mt][ks][1] = *(const uint32_t*)(Ax + (r + 8) * 72 + kk);
                afr[mt][ks][2] = *(const uint32_t*)(Ax + r * 72 + kk + 8);
                afr[mt][ks][3] = *(const uint32_t*)(Ax + (r + 8) * 72 + kk + 8);
            }
        }

        float acc[2][4][4];
        #pragma unroll
        for (int mt = 0; mt < 2; mt++)
            #pragma unroll
            for (int nt = 0; nt < 4; nt++)
                #pragma unroll
                for (int e = 0; e < 4; e++) acc[mt][nt][e] = 0.0f;

        #pragma unroll 1
        for (int kb = 0; kb < NBASIS; kb++) {
            float tac[2][4][4];
            #pragma unroll
            for (int mt = 0; mt < 2; mt++)
                #pragma unroll
                for (int nt = 0; nt < 4; nt++)
                    #pragma unroll
                    for (int e = 0; e < 4; e++) tac[mt][nt][e] = 0.0f;

            #pragma unroll
            for (int ks = 0; ks < 4; ks++) {
                #pragma unroll
                for (int nt = 0; nt < 4; nt++) {
                    int n = warp_n * 32 + nt * 8 + gid;
                    const __half* bp = Wh + (kb * 64 + n) * 72 + ks * 16 + tid4 * 2;
                    uint32_t b0 = *(const uint32_t*)bp;
                    uint32_t b1 = *(const uint32_t*)(bp + 8);
                    MMA16816(tac[0][nt], afr[0][ks], b0, b1);
                    MMA16816(tac[1][nt], afr[1][ks], b0, b1);
                }
            }

            // fold with fp32 bary
            #pragma unroll
            for (int mt = 0; mt < 2; mt++) {
                float blo = Bs[(rbase + mt * 16 + gid) * NBASIS + kb];
                float bhi = Bs[(rbase + mt * 16 + gid + 8) * NBASIS + kb];
                #pragma unroll
                for (int nt = 0; nt < 4; nt++) {
                    acc[mt][nt][0] += blo * tac[mt][nt][0];
                    acc[mt][nt][1] += blo * tac[mt][nt][1];
                    acc[mt][nt][2] += bhi * tac[mt][nt][2];
                    acc[mt][nt][3] += bhi * tac[mt][nt][3];
                }
            }
        }

        // ---- store 32x32 warp tile ----
        #pragma unroll
        for (int mt = 0; mt < 2; mt++) {
            int t = t0 + rbase + mt * 16 + gid;
            #pragma unroll
            for (int nt = 0; nt < 4; nt++) {
                int col = warp_n * 32 + nt * 8 + tid4 * 2;
                if (t < T)
                    *(float2*)&g_contrib[(size_t)t * C_OUT + col] =
                        make_float2(acc[mt][nt][0], acc[mt][nt][1]);
                if (t + 8 < T)
                    *(float2*)&g_contrib[(size_t)(t + 8) * C_OUT + col] =
                        make_float2(acc[mt][nt][2], acc[mt][nt][3]);
            }
        }
        __syncthreads();
    }
}

// ================= facet mean + bias + relu + fused BN stats =================
__global__ void facet_kernel(const int* __restrict__ cnt,
                             const float* __restrict__ bias, int F) {
    __shared__ float ssum[64], ssq[64];
    int tid = threadIdx.x;
    if (tid < 64) { ssum[tid] = 0.0f; ssq[tid] = 0.0f; }
    __syncthreads();

    int gw   = (blockIdx.x * blockDim.x + tid) >> 5;
    int lane = tid & 31;
    int nw   = (gridDim.x * blockDim.x) >> 5;
    float b0 = bias[lane];
    float b1 = bias[lane + 32];
    float a0 = 0.0f, a1 = 0.0f, q0 = 0.0f, q1 = 0.0f;

    for (int f = gw; f < F; f += nw) {
        int start = g_offs[f];
        int c = cnt[f];
        float s0 = 0.0f, s1 = 0.0f;
        for (int r = 0; r < c; r++) {
            const float* row = g_contrib + (size_t)(start + r) * C_OUT;
            s0 += row[lane];
            s1 += row[lane + 32];
        }
        float inv = (c > 0) ? (1.0f / (float)c) : 0.0f;
        float v0 = fmaxf(s0 * inv + b0, 0.0f);
        float v1 = fmaxf(s1 * inv + b1, 0.0f);
        g_prebn[(size_t)f * C_OUT + lane]      = v0;
        g_prebn[(size_t)f * C_OUT + lane + 32] = v1;
        a0 += v0; q0 += v0 * v0;
        a1 += v1; q1 += v1 * v1;
    }
    atomicAdd(&ssum[lane],      a0);
    atomicAdd(&ssq[lane],       q0);
    atomicAdd(&ssum[lane + 32], a1);
    atomicAdd(&ssq[lane + 32],  q1);
    __syncthreads();
    if (tid < 64) {
        atomicAdd(&g_stats[tid],      ssum[tid]);
        atomicAdd(&g_stats[64 + tid], ssq[tid]);
    }
}

__global__ void zero_stats_kernel() {
    if (threadIdx.x < 2 * C_OUT) g_stats[threadIdx.x] = 0.0f;
}

// ================= batchnorm apply =================
__global__ void bn_kernel(const float* __restrict__ gamma,
                          const float* __restrict__ beta,
                          float* __restrict__ out, int F) {
    int idx = blockIdx.x * blockDim.x + threadIdx.x;   // float4 index
    int total = F * (C_OUT / 4);
    float invF = 1.0f / (float)F;
    for (; idx < total; idx += gridDim.x * blockDim.x) {
        int o = (idx & 15) * 4;
        float4 v = *(const float4*)&g_prebn[(size_t)idx * 4];
        float4 r;
        #pragma unroll
        for (int j = 0; j < 4; j++) {
            float mu  = g_stats[o + j] * invF;
            float var = g_stats[C_OUT + o + j] * invF - mu * mu;
            float sc  = rsqrtf(var + BN_EPS) * gamma[o + j];
            float bb  = beta[o + j];
            float x   = (&v.x)[j];
            (&r.x)[j] = (x - mu) * sc + bb;
        }
        *(float4*)&out[(size_t)idx * 4] = r;
    }
}

// ================= launch =================
extern "C" void kernel_launch(void* const* d_in, const int* in_sizes, int n_in,
                              void* d_out, int out_size) {
    const float* X     = (const float*)d_in[0];
    const float* BARY  = (const float*)d_in[1];
    const float* W     = (const float*)d_in[2];
    const float* bias  = (const float*)d_in[3];
    const float* gamma = (const float*)d_in[4];
    const float* beta  = (const float*)d_in[5];
    const int*   cnt   = (const int*)d_in[6];

    int T = in_sizes[0] / C_IN;
    int F = in_sizes[6];
    int numTiles = (T + TILE_M - 1) / TILE_M;

    int sms = 148;
    cudaDeviceGetAttribute(&sms, cudaDevAttrMultiProcessorCount, 0);
    cudaFuncSetAttribute(gemm_mma_kernel, cudaFuncAttributeMaxDynamicSharedMemorySize, SMEM_GEMM);

    int nb = (F + 1023) / 1024;
    scan1_kernel<<<nb, 1024>>>(cnt, F);
    scan2_kernel<<<1, 1024>>>(nb);
    scan3_kernel<<<nb, 1024>>>(F);

    gemm_mma_kernel<<<sms, 512, SMEM_GEMM>>>(X, BARY, W, T, numTiles);

    zero_stats_kernel<<<1, 128>>>();
    facet_kernel<<<1024, 256>>>(cnt, bias, F);

    bn_kernel<<<2048, 256>>>(gamma, beta, (float*)d_out, F);
}

// round 4
// speedup vs baseline: 5.5538x; 1.1453x over previous
#include <cuda_runtime.h>
#include <cuda_fp16.h>
#include <math.h>
#include <stdint.h>

#define C_IN   64
#define C_OUT  64
#define NBASIS 9
#define TILE_M 128
#define MAX_T  1600000
#define MAX_F  400000
#define BN_EPS 1e-3f

// ---- scratch (device globals; no allocation allowed) ----
__device__ __half g_contrib[(size_t)MAX_T * C_OUT];  // 204.8 MB (fp16)
__device__ float  g_prebn[(size_t)MAX_F * C_OUT];    // 102.4 MB
__device__ int    g_offs[MAX_F];
__device__ int    g_blk[1024];
__device__ float  g_stats[2 * C_OUT];

// ================= exclusive-scan of num_texture =================
__global__ void scan1_kernel(const int* __restrict__ cnt, int F) {
    __shared__ int s[1024];
    int tid = threadIdx.x;
    int f = blockIdx.x * 1024 + tid;
    int c = (f < F) ? cnt[f] : 0;
    s[tid] = c;
    __syncthreads();
    for (int off = 1; off < 1024; off <<= 1) {
        int v = (tid >= off) ? s[tid - off] : 0;
        __syncthreads();
        s[tid] += v;
        __syncthreads();
    }
    if (f < F) g_offs[f] = s[tid] - c;
    if (tid == 1023) g_blk[blockIdx.x] = s[1023];
}
__global__ void scan2_kernel(int nb) {
    __shared__ int s[1024];
    int tid = threadIdx.x;
    int c = (tid < nb) ? g_blk[tid] : 0;
    s[tid] = c;
    __syncthreads();
    for (int off = 1; off < 1024; off <<= 1) {
        int v = (tid >= off) ? s[tid - off] : 0;
        __syncthreads();
        s[tid] += v;
        __syncthreads();
    }
    if (tid < nb) g_blk[tid] = s[tid] - c;
}
__global__ void scan3_kernel(int F) {
    int f = blockIdx.x * 1024 + threadIdx.x;
    if (f < F) g_offs[f] += g_blk[blockIdx.x];
}

// ================= mma.sync GEMM (2 CTAs/SM) =================
// contrib[t,o] = sum_k bary[t,k] * ( sum_i x[t,i] * W[o,i,k] )
//
// SMEM per CTA:
//   Wh : [(k*64 + o)*72 + i] fp16   9*64*72*2 = 82944 B
//   Ax : [t*72 + i]          fp16   128*72*2  = 18432 B
//   Bs : [t*9 + k]           fp32   128*9*4   =  4608 B
#define SM_WH   0
#define SM_AX   82944
#define SM_BS   (SM_AX + TILE_M * 72 * 2)              // 101376
#define SMEM_GEMM (SM_BS + TILE_M * NBASIS * 4)        // 105984

#define MMA16816(d, a, b0, b1)                                              \
    asm volatile(                                                           \
        "mma.sync.aligned.m16n8k16.row.col.f32.f16.f16.f32 "                \
        "{%0,%1,%2,%3},{%4,%5,%6,%7},{%8,%9},{%0,%1,%2,%3};"                \
        : "+f"((d)[0]), "+f"((d)[1]), "+f"((d)[2]), "+f"((d)[3])            \
        : "r"((a)[0]), "r"((a)[1]), "r"((a)[2]), "r"((a)[3]),               \
          "r"(b0), "r"(b1))

__global__ void __launch_bounds__(256, 2) gemm_mma_kernel(
    const float* __restrict__ X,     // [T, 64]
    const float* __restrict__ BARY,  // [T, 9]
    const float* __restrict__ W,     // [64, 64, 9]  (o, i, k)
    int T, int numTiles)
{
    extern __shared__ char sm[];
    __half* Wh = (__half*)(sm + SM_WH);
    __half* Ax = (__half*)(sm + SM_AX);
    float*  Bs = (float*)(sm + SM_BS);

    const int tid  = threadIdx.x;
    const int wid  = tid >> 5;
    const int lane = tid & 31;
    const int gid  = lane >> 2;     // group id (0..7)
    const int tid4 = lane & 3;      // thread in group
    const int warp_m = wid >> 1;    // 0..3 : 32-row band
    const int warp_n = wid & 1;     // 0..1 : 32-col band

    // ---- convert W once: Wh[k][o][i] fp16 ----
    for (int idx = tid; idx < C_OUT * C_IN * NBASIS; idx += 256) {
        int o   = idx / (C_IN * NBASIS);
        int rem = idx - o * (C_IN * NBASIS);
        int i   = rem / NBASIS;
        int k   = rem - i * NBASIS;
        Wh[(k * 64 + o) * 72 + i] = __float2half_rn(W[idx]);
    }
    __syncthreads();

    const int rbase = warp_m * 32;

    for (int tile = blockIdx.x; tile < numTiles; tile += gridDim.x) {
        const int t0 = tile * TILE_M;

        // ---- load X tile -> fp16 Ax[t][i] (2 threads per row) ----
        {
            int row = tid >> 1;      // 0..127
            int hf  = tid & 1;
            int t = t0 + row;
            uint32_t pk[16];
            if (t < T) {
                const float4* xp = (const float4*)(X + (size_t)t * C_IN + hf * 32);
                #pragma unroll
                for (int j = 0; j < 8; j++) {
                    float4 v = xp[j];
                    __half2 h0 = __floats2half2_rn(v.x, v.y);
                    __half2 h1 = __floats2half2_rn(v.z, v.w);
                    pk[2 * j]     = *(uint32_t*)&h0;
                    pk[2 * j + 1] = *(uint32_t*)&h1;
                }
            } else {
                #pragma unroll
                for (int j = 0; j < 16; j++) pk[j] = 0u;
            }
            uint4* dst = (uint4*)(Ax + row * 72 + hf * 32);
            #pragma unroll
            for (int c = 0; c < 4; c++)
                dst[c] = make_uint4(pk[4 * c], pk[4 * c + 1], pk[4 * c + 2], pk[4 * c + 3]);
        }
        // ---- bary tile (fp32) ----
        {
            int limit = (T - t0) * NBASIS;
            for (int idx = tid; idx < TILE_M * NBASIS; idx += 256)
                Bs[idx] = (idx < limit) ? BARY[(size_t)t0 * NBASIS + idx] : 0.0f;
        }
        __syncthreads();

        // ---- A fragments (once per tile, reused for all 9 bases) ----
        uint32_t afr[2][4][4];
        #pragma unroll
        for (int mt = 0; mt < 2; mt++) {
            int r = rbase + mt * 16 + gid;
            #pragma unroll
            for (int ks = 0; ks < 4; ks++) {
                int kk = ks * 16 + tid4 * 2;
                afr[mt][ks][0] = *(const uint32_t*)(Ax + r * 72 + kk);
                afr[mt][ks][1] = *(const uint32_t*)(Ax + (r + 8) * 72 + kk);
                afr[mt][ks][2] = *(const uint32_t*)(Ax + r * 72 + kk + 8);
                afr[mt][ks][3] = *(const uint32_t*)(Ax + (r + 8) * 72 + kk + 8);
            }
        }

        float acc[2][4][4];
        #pragma unroll
        for (int mt = 0; mt < 2; mt++)
            #pragma unroll
            for (int nt = 0; nt < 4; nt++)
                #pragma unroll
                for (int e = 0; e < 4; e++) acc[mt][nt][e] = 0.0f;

        #pragma unroll 1
        for (int kb = 0; kb < NBASIS; kb++) {
            float tac[2][4][4];
            #pragma unroll
            for (int mt = 0; mt < 2; mt++)
                #pragma unroll
                for (int nt = 0; nt < 4; nt++)
                    #pragma unroll
                    for (int e = 0; e < 4; e++) tac[mt][nt][e] = 0.0f;

            #pragma unroll
            for (int ks = 0; ks < 4; ks++) {
                #pragma unroll
                for (int nt = 0; nt < 4; nt++) {
                    int n = warp_n * 32 + nt * 8 + gid;
                    const __half* bp = Wh + (kb * 64 + n) * 72 + ks * 16 + tid4 * 2;
                    uint32_t b0 = *(const uint32_t*)bp;
                    uint32_t b1 = *(const uint32_t*)(bp + 8);
                    MMA16816(tac[0][nt], afr[0][ks], b0, b1);
                    MMA16816(tac[1][nt], afr[1][ks], b0, b1);
                }
            }

            // fold with fp32 bary
            #pragma unroll
            for (int mt = 0; mt < 2; mt++) {
                float blo = Bs[(rbase + mt * 16 + gid) * NBASIS + kb];
                float bhi = Bs[(rbase + mt * 16 + gid + 8) * NBASIS + kb];
                #pragma unroll
                for (int nt = 0; nt < 4; nt++) {
                    acc[mt][nt][0] += blo * tac[mt][nt][0];
                    acc[mt][nt][1] += blo * tac[mt][nt][1];
                    acc[mt][nt][2] += bhi * tac[mt][nt][2];
                    acc[mt][nt][3] += bhi * tac[mt][nt][3];
                }
            }
        }

        // ---- store 32x32 warp tile as fp16 ----
        #pragma unroll
        for (int mt = 0; mt < 2; mt++) {
            int t = t0 + rbase + mt * 16 + gid;
            #pragma unroll
            for (int nt = 0; nt < 4; nt++) {
                int col = warp_n * 32 + nt * 8 + tid4 * 2;
                if (t < T) {
                    __half2 h = __floats2half2_rn(acc[mt][nt][0], acc[mt][nt][1]);
                    *(__half2*)&g_contrib[(size_t)t * C_OUT + col] = h;
                }
                if (t + 8 < T) {
                    __half2 h = __floats2half2_rn(acc[mt][nt][2], acc[mt][nt][3]);
                    *(__half2*)&g_contrib[(size_t)(t + 8) * C_OUT + col] = h;
                }
            }
        }
        __syncthreads();
    }
}

// ================= facet mean + bias + relu + fused BN stats =================
// Warp per facet group; lane owns channels {2*lane, 2*lane+1} (half2 reads).
__global__ void facet_kernel(const int* __restrict__ cnt,
                             const float* __restrict__ bias, int F) {
    __shared__ float ssum[64], ssq[64];
    int tid = threadIdx.x;
    if (tid < 64) { ssum[tid] = 0.0f; ssq[tid] = 0.0f; }
    __syncthreads();

    int gw   = (blockIdx.x * blockDim.x + tid) >> 5;
    int lane = tid & 31;
    int nw   = (gridDim.x * blockDim.x) >> 5;
    float b0 = bias[2 * lane];
    float b1 = bias[2 * lane + 1];
    float a0 = 0.0f, a1 = 0.0f, q0 = 0.0f, q1 = 0.0f;

    for (int f = gw; f < F; f += nw) {
        int start = g_offs[f];
        int c = cnt[f];
        float s0 = 0.0f, s1 = 0.0f;
        for (int r = 0; r < c; r++) {
            const __half2* row = (const __half2*)(g_contrib + (size_t)(start + r) * C_OUT);
            float2 v = __half22float2(row[lane]);
            s0 += v.x;
            s1 += v.y;
        }
        float inv = (c > 0) ? (1.0f / (float)c) : 0.0f;
        float v0 = fmaxf(s0 * inv + b0, 0.0f);
        float v1 = fmaxf(s1 * inv + b1, 0.0f);
        *(float2*)&g_prebn[(size_t)f * C_OUT + 2 * lane] = make_float2(v0, v1);
        a0 += v0; q0 += v0 * v0;
        a1 += v1; q1 += v1 * v1;
    }
    atomicAdd(&ssum[2 * lane],     a0);
    atomicAdd(&ssq[2 * lane],      q0);
    atomicAdd(&ssum[2 * lane + 1], a1);
    atomicAdd(&ssq[2 * lane + 1],  q1);
    __syncthreads();
    if (tid < 64) {
        atomicAdd(&g_stats[tid],      ssum[tid]);
        atomicAdd(&g_stats[64 + tid], ssq[tid]);
    }
}

__global__ void zero_stats_kernel() {
    if (threadIdx.x < 2 * C_OUT) g_stats[threadIdx.x] = 0.0f;
}

// ================= batchnorm apply =================
__global__ void bn_kernel(const float* __restrict__ gamma,
                          const float* __restrict__ beta,
                          float* __restrict__ out, int F) {
    int idx = blockIdx.x * blockDim.x + threadIdx.x;   // float4 index
    int total = F * (C_OUT / 4);
    float invF = 1.0f / (float)F;
    for (; idx < total; idx += gridDim.x * blockDim.x) {
        int o = (idx & 15) * 4;
        float4 v = *(const float4*)&g_prebn[(size_t)idx * 4];
        float4 r;
        #pragma unroll
        for (int j = 0; j < 4; j++) {
            float mu  = g_stats[o + j] * invF;
            float var = g_stats[C_OUT + o + j] * invF - mu * mu;
            float sc  = rsqrtf(var + BN_EPS) * gamma[o + j];
            float bb  = beta[o + j];
            float x   = (&v.x)[j];
            (&r.x)[j] = (x - mu) * sc + bb;
        }
        *(float4*)&out[(size_t)idx * 4] = r;
    }
}

// ================= launch =================
extern "C" void kernel_launch(void* const* d_in, const int* in_sizes, int n_in,
                              void* d_out, int out_size) {
    const float* X     = (const float*)d_in[0];
    const float* BARY  = (const float*)d_in[1];
    const float* W     = (const float*)d_in[2];
    const float* bias  = (const float*)d_in[3];
    const float* gamma = (const float*)d_in[4];
    const float* beta  = (const float*)d_in[5];
    const int*   cnt   = (const int*)d_in[6];

    int T = in_sizes[0] / C_IN;
    int F = in_sizes[6];
    int numTiles = (T + TILE_M - 1) / TILE_M;

    int sms = 148;
    cudaDeviceGetAttribute(&sms, cudaDevAttrMultiProcessorCount, 0);
    cudaFuncSetAttribute(gemm_mma_kernel, cudaFuncAttributeMaxDynamicSharedMemorySize, SMEM_GEMM);

    int nb = (F + 1023) / 1024;
    scan1_kernel<<<nb, 1024>>>(cnt, F);
    scan2_kernel<<<1, 1024>>>(nb);
    scan3_kernel<<<nb, 1024>>>(F);

    gemm_mma_kernel<<<2 * sms, 256, SMEM_GEMM>>>(X, BARY, W, T, numTiles);

    zero_stats_kernel<<<1, 128>>>();
    facet_kernel<<<2048, 256>>>(cnt, bias, F);

    bn_kernel<<<2048, 256>>>(gamma, beta, (float*)d_out, F);
}